// round 1
// baseline (speedup 1.0000x reference)
#include <cuda_runtime.h>
#include <math.h>

#define BB 4
#define CC 1024
#define TT 4096
#define HH 16
#define DD 64
#define BT (BB*TT)        // 16384
#define SPLIT 8
#define TCH (TT/SPLIT)    // 512

// Scratch (alloc-free: __device__ globals)
__device__ float g_q[(size_t)BT*CC];
__device__ float g_k[(size_t)BT*CC];
__device__ float g_v[(size_t)BT*CC];
__device__ float g_attn[(size_t)BT*CC];
__device__ float g_kv[BB*HH*DD*DD];
__device__ float g_ksum[BB*HH*DD];

// ---------------------------------------------------------------------------
// QKV projection GEMM: out[bt, n] = act( sum_k xt[bt,k] * W[n,k] + bias[n] )
// xt[bt,k] = x[b, k, t]  (b = bt/T, t = bt%T)
// ACT=1: elu(v)+1 = v>0 ? v+1 : exp(v);   ACT=0: identity
// Tiles: 64(M=bt) x 64(N) x 16(K), 256 threads, 4x4 microtile
// ---------------------------------------------------------------------------
template<int ACT>
__global__ void proj_kernel(const float* __restrict__ x, const float* __restrict__ W,
                            const float* __restrict__ bias, float* __restrict__ out)
{
    __shared__ float As[16][65];
    __shared__ float Bs[16][65];
    const int bm = blockIdx.x * 64;   // bt tile origin (never crosses batch: T%64==0)
    const int bn = blockIdx.y * 64;
    const int b  = bm / TT;
    const int t0 = bm % TT;
    const int tid = threadIdx.x;
    const int tx = tid & 15, ty = tid >> 4;
    float acc[4][4] = {};
    const float* xb = x + (size_t)b * CC * TT + t0;

    for (int k0 = 0; k0 < CC; k0 += 16) {
        #pragma unroll
        for (int r = 0; r < 4; r++) {               // A: coalesced over t
            int i = tid + r*256;
            int kk = i >> 6, m = i & 63;
            As[kk][m] = xb[(size_t)(k0+kk)*TT + m];
        }
        #pragma unroll
        for (int r = 0; r < 4; r++) {               // B: 64B segments along k
            int i = tid + r*256;
            int kk = i & 15, n = i >> 4;
            Bs[kk][n] = W[(size_t)(bn+n)*CC + k0 + kk];
        }
        __syncthreads();
        #pragma unroll
        for (int kk = 0; kk < 16; kk++) {
            float a[4], bb[4];
            #pragma unroll
            for (int i = 0; i < 4; i++) a[i]  = As[kk][ty*4+i];
            #pragma unroll
            for (int j = 0; j < 4; j++) bb[j] = Bs[kk][tx*4+j];
            #pragma unroll
            for (int i = 0; i < 4; i++)
                #pragma unroll
                for (int j = 0; j < 4; j++)
                    acc[i][j] = fmaf(a[i], bb[j], acc[i][j]);
        }
        __syncthreads();
    }

    #pragma unroll
    for (int i = 0; i < 4; i++) {
        int m = bm + ty*4 + i;
        #pragma unroll
        for (int j = 0; j < 4; j++) {
            int n = bn + tx*4 + j;
            float v = acc[i][j] + bias[n];
            if (ACT) v = (v > 0.f) ? (v + 1.f) : expf(v);
            out[(size_t)m*CC + n] = v;
        }
    }
}

// ---------------------------------------------------------------------------
// Zero the kv / ksum accumulators (graph replays require re-zeroing each call)
// ---------------------------------------------------------------------------
__global__ void zero_kernel()
{
    int i = blockIdx.x * 256 + threadIdx.x;
    if (i < BB*HH*DD*DD) g_kv[i] = 0.f;
    if (i < BB*HH*DD)    g_ksum[i] = 0.f;
}

// ---------------------------------------------------------------------------
// kv[b,h,d,e] = sum_t k[b,t,h,d] * v[b,t,h,e];  ksum[b,h,d] = sum_t k[b,t,h,d]
// grid = B*H*SPLIT blocks, 256 threads. Each block reduces a T-chunk of 512,
// atomically merging into the global accumulators.
// thread owns (d = tid/4, e in [(tid&3)*16, +16))  → 16 accumulators
// ---------------------------------------------------------------------------
__global__ void kv_kernel()
{
    __shared__ float Ks[32][64];
    __shared__ float Vs[32][64];
    const int blk = blockIdx.x;
    const int sp  = blk & (SPLIT-1);
    const int bh  = blk / SPLIT;
    const int b = bh / HH, h = bh % HH;
    const int tid = threadIdx.x;
    const int d  = tid >> 2;
    const int e0 = (tid & 3) * 16;
    float acc[16] = {};
    float ks_local = 0.f;
    const size_t base = (size_t)(b*TT + sp*TCH) * CC + h*DD;

    for (int t0 = 0; t0 < TCH; t0 += 32) {
        #pragma unroll
        for (int r = 0; r < 8; r++) {
            int i = tid + r*256;
            int ttl = i >> 6, dd2 = i & 63;
            size_t g = base + (size_t)(t0+ttl)*CC + dd2;
            Ks[ttl][dd2] = g_k[g];
            Vs[ttl][dd2] = g_v[g];
        }
        __syncthreads();
        #pragma unroll
        for (int ttl = 0; ttl < 32; ttl++) {
            float kvv = Ks[ttl][d];
            #pragma unroll
            for (int j = 0; j < 16; j++)
                acc[j] = fmaf(kvv, Vs[ttl][e0+j], acc[j]);
        }
        if (tid < 64) {
            #pragma unroll
            for (int ttl = 0; ttl < 32; ttl++) ks_local += Ks[ttl][tid];
        }
        __syncthreads();
    }

    float* kvout = &g_kv[(size_t)((b*HH+h)*DD + d)*DD];
    #pragma unroll
    for (int j = 0; j < 16; j++) atomicAdd(&kvout[e0+j], acc[j]);
    if (tid < 64) atomicAdd(&g_ksum[(b*HH+h)*DD + tid], ks_local);
}

// ---------------------------------------------------------------------------
// attn[bt, h*64+e] = (sum_d q[bt,h,d]*kv[b,h,d,e]) / (sum_d q[bt,h,d]*ksum[b,h,d] + 1e-6)
// One block per bt. kv (1 MB per full tensor) stays L2-resident.
// ---------------------------------------------------------------------------
__global__ void attn_kernel()
{
    __shared__ float qs[CC];
    __shared__ float zr[HH];
    const int bt = blockIdx.x;
    const int b  = bt / TT;
    const int tid = threadIdx.x;

    #pragma unroll
    for (int r = 0; r < 4; r++)
        qs[tid + r*256] = g_q[(size_t)bt*CC + tid + r*256];
    __syncthreads();

    if (tid < HH) {
        float z = 0.f;
        const float* ks = &g_ksum[(b*HH + tid)*DD];
        #pragma unroll
        for (int dd = 0; dd < DD; dd++) z = fmaf(qs[tid*DD+dd], ks[dd], z);
        zr[tid] = 1.f / (z + 1e-6f);
    }
    __syncthreads();

    #pragma unroll
    for (int r = 0; r < 4; r++) {
        int o = tid + r*256;
        int h = o >> 6, e = o & 63;
        const float* kvp = &g_kv[(size_t)((b*HH+h)*DD)*DD + e];
        const float* qp  = &qs[h*DD];
        float acc = 0.f;
        #pragma unroll
        for (int dd = 0; dd < DD; dd++)
            acc = fmaf(qp[dd], kvp[dd*DD], acc);     // coalesced over e across lanes
        g_attn[(size_t)bt*CC + o] = acc * zr[h];
    }
}

// ---------------------------------------------------------------------------
// Output projection + bias + residual + transpose:
// out[b, n, t] = sum_k attn[bt,k]*Wo[n,k] + bo[n] + x[b, n, t]
// ---------------------------------------------------------------------------
__global__ void out_kernel(const float* __restrict__ x, const float* __restrict__ Wo,
                           const float* __restrict__ bo, float* __restrict__ out)
{
    __shared__ float As[16][65];
    __shared__ float Bs[16][65];
    const int bm = blockIdx.x * 64;   // bt tile
    const int bn = blockIdx.y * 64;   // output channel tile
    const int b  = bm / TT;
    const int t0 = bm % TT;
    const int tid = threadIdx.x;
    const int tx = tid & 15, ty = tid >> 4;
    float acc[4][4] = {};

    for (int k0 = 0; k0 < CC; k0 += 16) {
        #pragma unroll
        for (int r = 0; r < 4; r++) {               // A: attn is [bt, C] row-major
            int i = tid + r*256;
            int kk = i & 15, m = i >> 4;
            As[kk][m] = g_attn[(size_t)(bm+m)*CC + k0 + kk];
        }
        #pragma unroll
        for (int r = 0; r < 4; r++) {
            int i = tid + r*256;
            int kk = i & 15, n = i >> 4;
            Bs[kk][n] = Wo[(size_t)(bn+n)*CC + k0 + kk];
        }
        __syncthreads();
        #pragma unroll
        for (int kk = 0; kk < 16; kk++) {
            float a[4], bb[4];
            #pragma unroll
            for (int i = 0; i < 4; i++) a[i]  = As[kk][ty*4+i];
            #pragma unroll
            for (int j = 0; j < 4; j++) bb[j] = Bs[kk][tx*4+j];
            #pragma unroll
            for (int i = 0; i < 4; i++)
                #pragma unroll
                for (int j = 0; j < 4; j++)
                    acc[i][j] = fmaf(a[i], bb[j], acc[i][j]);
        }
        __syncthreads();
    }

    #pragma unroll
    for (int j = 0; j < 4; j++) {
        int n = bn + tx*4 + j;
        float bn_bias = bo[n];
        #pragma unroll
        for (int i = 0; i < 4; i++) {
            int m = ty*4 + i;
            size_t idx = (size_t)b*CC*TT + (size_t)n*TT + t0 + m;
            out[idx] = acc[i][j] + bn_bias + x[idx];
        }
    }
}

// ---------------------------------------------------------------------------
extern "C" void kernel_launch(void* const* d_in, const int* in_sizes, int n_in,
                              void* d_out, int out_size)
{
    const float* x  = (const float*)d_in[0];
    const float* Wq = (const float*)d_in[1];
    const float* bq = (const float*)d_in[2];
    const float* Wk = (const float*)d_in[3];
    const float* bk = (const float*)d_in[4];
    const float* Wv = (const float*)d_in[5];
    const float* bv = (const float*)d_in[6];
    const float* Wo = (const float*)d_in[7];
    const float* bo = (const float*)d_in[8];
    float* out = (float*)d_out;

    float *gq, *gk, *gv;
    cudaGetSymbolAddress((void**)&gq, g_q);
    cudaGetSymbolAddress((void**)&gk, g_k);
    cudaGetSymbolAddress((void**)&gv, g_v);

    dim3 grid(BT/64, CC/64);
    proj_kernel<1><<<grid, 256>>>(x, Wq, bq, gq);
    proj_kernel<1><<<grid, 256>>>(x, Wk, bk, gk);
    proj_kernel<0><<<grid, 256>>>(x, Wv, bv, gv);
    zero_kernel<<<(BB*HH*DD*DD + 255)/256, 256>>>();
    kv_kernel<<<BB*HH*SPLIT, 256>>>();
    attn_kernel<<<BT, 256>>>();
    out_kernel<<<grid, 256>>>(x, Wo, bo, out);
}